// round 16
// baseline (speedup 1.0000x reference)
#include <cuda_runtime.h>

#define NN 2048
#define BB 32
#define TT 512
#define NT 16            // n-rows per CTA
#define GRIDSZ 128       // 128 CTAs * 16 rows = 2048
#define NTHR 512
#define NWARP 16
#define NSLICE 16        // 1 reduced slice per warp (xor8 + xor16 reduce)
#define PADB 34          // padded batch stride (float2 units) — >=32 and EVEN
#define JSTR 20          // Jt row stride in floats (16 data + 4 pad)

#define F_DT   1e-4f
#define F_U    0.3f
#define F_TAU  0.008f
#define F_TAUF 1.5f
#define F_TAUD 0.3f
#define F_ALPHA 1.5f
#define F_IB   8.0f
#define F_JEI  1.1f
#define F_JIE  2.2f

typedef unsigned long long ull;

// ---- persistent device state (double-buffered across steps) ----
__device__ float g_uxR[2][NN][BB];            // u*x*R(h), layout [m][b]
__device__ float g_partialSumR[2][GRIDSZ][BB];// per-CTA partial of sum_n R(h)
__device__ float g_partialOut[2][GRIDSZ][BB]; // per-CTA partial of readout
__device__ unsigned g_flags[GRIDSZ][32];      // per-CTA epoch flag (128B apart)

// packed fp32x2 fma, accumulator form: d = a*b + d
__device__ __forceinline__ void ffma2u(ull& d, ull a, ull b) {
    asm("fma.rn.f32x2 %0, %1, %2, %0;" : "+l"(d) : "l"(a), "l"(b));
}
__device__ __forceinline__ ull pack2(float v) {
    ull r; asm("mov.b64 %0, {%1, %1};" : "=l"(r) : "f"(v)); return r;
}

// R(h) = alpha * softplus(h/alpha), MUFU-based
__device__ __forceinline__ float rate_fn(float h) {
    float z = h * (1.0f / F_ALPHA);
    float sp = fmaxf(z, 0.0f) + __logf(1.0f + __expf(-fabsf(z)));
    return F_ALPHA * sp;
}

// warp-collective: wait until producer flags[8*warp .. 8*warp+7] >= target
__device__ __forceinline__ void waitProducers(int warp, int l8, unsigned target) {
    const unsigned* fp = &g_flags[warp * 8 + l8][0];
    unsigned v;
    do {
        asm volatile("ld.acquire.gpu.global.u32 %0, [%1];"
                     : "=r"(v) : "l"(fp) : "memory");
    } while (__any_sync(0xFFFFFFFFu, v < target));
}

__global__ void init_kernel() {
    int i = blockIdx.x * blockDim.x + threadIdx.x;
    int stride = gridDim.x * blockDim.x;
    const float R0 = F_ALPHA * 0.6931471805599453f;  // rate(0)
    const float v = F_U * R0;                        // u0*x0*R0
    float* u0p = &g_uxR[0][0][0];
    for (int k = i; k < NN * BB; k += stride) u0p[k] = v;
    float* ps = &g_partialSumR[0][0][0];
    for (int k = i; k < GRIDSZ * BB; k += stride) ps[k] = (float)NT * R0;
    unsigned* fl = &g_flags[0][0];
    for (int k = i; k < GRIDSZ * 32; k += stride) fl[k] = 0u;
}

__global__ void __launch_bounds__(NTHR, 1)
step_kernel(const float* __restrict__ inp, const float* __restrict__ W_in,
            const float* __restrict__ J,   const float* __restrict__ W_out,
            float* __restrict__ out)
{
    extern __shared__ float smem[];
    float*  Jt     = smem;                             // [NN][JSTR] transposed J
    float2* redp   = (float2*)(Jt + (size_t)NN * JSTR);// [NSLICE][8 np][PADB]
    float*  sPartA = (float*)(redp + (size_t)NSLICE * 8 * PADB); // [2][NWARP][BB]
    float*  sPartB = sPartA + 2 * NWARP * BB;          // [2][NWARP][BB]

    float* all_h  = out;
    float* all_u  = out + (size_t)TT * BB * NN;
    float* all_x  = out + (size_t)2 * TT * BB * NN;
    float* all_hI = out + (size_t)3 * TT * BB * NN;
    float* outputs = all_hI + (size_t)TT * BB;

    const int tid  = threadIdx.x;
    const int bid  = blockIdx.x;
    const int warp = tid >> 5;
    const int lane = tid & 31;
    const int strm = lane >> 3;        // 0..3  m-stream within warp
    const int l8   = lane & 7;         // 0..7  -> batches [4*l8, 4*l8+4)
    const int n0   = bid * NT;

    // update-phase mapping: thread -> (batch ub, single neuron n0+un)
    const int ub = tid >> 4;           // 0..31
    const int un = tid & 15;           // 0..15

    const float invTau  = 1.0f / F_TAU;
    const float invTauF = 1.0f / F_TAUF;
    const float invTauD = 1.0f / F_TAUD;

    // ---- stage J transposed ONCE: Jt[m][n_local], row stride JSTR ----
    #pragma unroll 4
    for (int it = 0; it < 16; ++it) {
        int idx = tid + it * NTHR;     // 0..8191 (16 rows * 512 float4)
        int r   = idx >> 9;            // 0..15
        int c4  = idx & 511;           // float4 col (m/4)
        float4 v = *(const float4*)(J + (size_t)(n0 + r) * NN + c4 * 4);
        float* dst = Jt + (size_t)(c4 * 4) * JSTR + r;
        dst[0 * JSTR] = v.x;
        dst[1 * JSTR] = v.y;
        dst[2 * JSTR] = v.z;
        dst[3 * JSTR] = v.w;
    }

    const float wi = W_in[n0 + un];
    const float wo = W_out[n0 + un];
    __syncthreads();

    // persistent per-thread state (h_I replicated, deterministic identical)
    float hr = 0.0f, h_Ir = 0.0f;
    const float R0c = rate_fn(0.0f);
    float RIr = R0c;                                       // rate(h_I(0))
    float un2 = F_U + (F_U * (1.0f - F_U) * R0c) * F_DT;   // u(1)
    float xn2 = 1.0f - (F_U * R0c) * F_DT;                 // x(1)
    float invalr = inp[ub];                                 // inp(0)

    // GEMM: iteration mi processes m = warp*128 + mi*4 + strm
    const int mfirst = warp * 128 + strm;
    const ull ONE2 = pack2(1.0f);

    for (int t = 0; t < TT; ++t) {
        const int cur = t & 1, nxt = cur ^ 1;
        float* sPA = sPartA + cur * (NWARP * BB);   // this step's staging
        float* sPB = sPartB + cur * (NWARP * BB);

        // ---- wait for THIS warp's 8 producer CTAs (epoch >= t) ----------
        // (no CTA-wide barrier here: deferred work of step t-1 overlaps
        //  this poll; smem staging is double-buffered by parity)
        waitProducers(warp, l8, (unsigned)t);

        // ===== GEMM: 4 m-streams x 8 lanes x 4 batches x 16 n ===========
        const float* ubaseF = &g_uxR[cur][0][0] + (size_t)mfirst * BB + 4 * l8;

        ull acc[8][4];
        #pragma unroll
        for (int p = 0; p < 8; ++p)
            #pragma unroll
            for (int b = 0; b < 4; ++b) acc[p][b] = 0ull;

        float4 upf[2];
        upf[0] = __ldcg((const float4*)(ubaseF + 0 * 4 * BB));
        upf[1] = __ldcg((const float4*)(ubaseF + 1 * 4 * BB));

        #pragma unroll 4
        for (int mi = 0; mi < 32; ++mi) {
            const float4 u4 = upf[mi & 1];
            if (mi < 30)
                upf[mi & 1] = __ldcg((const float4*)(ubaseF + (size_t)(mi + 2) * 4 * BB));

            const int m = mfirst + mi * 4;
            const ulonglong2* jq = (const ulonglong2*)(Jt + (size_t)m * JSTR);
            ulonglong2 q0 = jq[0];
            ulonglong2 q1 = jq[1];
            ulonglong2 q2 = jq[2];
            ulonglong2 q3 = jq[3];

            const ull ub0 = pack2(u4.x);
            const ull ub1 = pack2(u4.y);
            const ull ub2p = pack2(u4.z);
            const ull ub3 = pack2(u4.w);

            ffma2u(acc[0][0], q0.x, ub0); ffma2u(acc[0][1], q0.x, ub1);
            ffma2u(acc[0][2], q0.x, ub2p); ffma2u(acc[0][3], q0.x, ub3);
            ffma2u(acc[1][0], q0.y, ub0); ffma2u(acc[1][1], q0.y, ub1);
            ffma2u(acc[1][2], q0.y, ub2p); ffma2u(acc[1][3], q0.y, ub3);
            ffma2u(acc[2][0], q1.x, ub0); ffma2u(acc[2][1], q1.x, ub1);
            ffma2u(acc[2][2], q1.x, ub2p); ffma2u(acc[2][3], q1.x, ub3);
            ffma2u(acc[3][0], q1.y, ub0); ffma2u(acc[3][1], q1.y, ub1);
            ffma2u(acc[3][2], q1.y, ub2p); ffma2u(acc[3][3], q1.y, ub3);
            ffma2u(acc[4][0], q2.x, ub0); ffma2u(acc[4][1], q2.x, ub1);
            ffma2u(acc[4][2], q2.x, ub2p); ffma2u(acc[4][3], q2.x, ub3);
            ffma2u(acc[5][0], q2.y, ub0); ffma2u(acc[5][1], q2.y, ub1);
            ffma2u(acc[5][2], q2.y, ub2p); ffma2u(acc[5][3], q2.y, ub3);
            ffma2u(acc[6][0], q3.x, ub0); ffma2u(acc[6][1], q3.x, ub1);
            ffma2u(acc[6][2], q3.x, ub2p); ffma2u(acc[6][3], q3.x, ub3);
            ffma2u(acc[7][0], q3.y, ub0); ffma2u(acc[7][1], q3.y, ub1);
            ffma2u(acc[7][2], q3.y, ub2p); ffma2u(acc[7][3], q3.y, ub3);
        }

        // ---- issue cross-CTA partial loads (hidden by the reduce below) -
        float pA[8], pB[8];
        {
            const float* pS = &g_partialSumR[cur][0][0];
            #pragma unroll
            for (int c = 0; c < 8; ++c) pA[c] = __ldcg(pS + (warp * 8 + c) * BB + lane);
            if (bid == 0 && t > 0) {
                const float* pO = &g_partialOut[cur][0][0];
                #pragma unroll
                for (int c = 0; c < 8; ++c) pB[c] = __ldcg(pO + (warp * 8 + c) * BB + lane);
            }
        }

        // ----- reduce the 4 streams in-register (same n, same batches) ---
        #pragma unroll
        for (int p = 0; p < 8; ++p)
            #pragma unroll
            for (int b = 0; b < 4; ++b) {
                ull o1 = __shfl_xor_sync(0xFFFFFFFFu, acc[p][b], 8);
                ffma2u(acc[p][b], o1, ONE2);
                ull o2 = __shfl_xor_sync(0xFFFFFFFFu, acc[p][b], 16);
                ffma2u(acc[p][b], o2, ONE2);
            }

        // lanes 0..7 hold full warp partials; store slice = warp
        if (strm == 0) {
            float2* rw = redp + (size_t)warp * 8 * PADB + 4 * l8;
            #pragma unroll
            for (int p = 0; p < 8; ++p) {
                ulonglong2 v0; v0.x = acc[p][0]; v0.y = acc[p][1];
                ulonglong2 v1; v1.x = acc[p][2]; v1.y = acc[p][3];
                *(ulonglong2*)(rw + p * PADB)     = v0;
                *(ulonglong2*)(rw + p * PADB + 2) = v1;
            }
        }

        // stage cross-CTA partial sums into this-parity smem buffers
        {
            float sA = pA[0] + pA[1] + pA[2] + pA[3] + pA[4] + pA[5] + pA[6] + pA[7];
            sPA[warp * BB + lane] = sA;
            if (bid == 0 && t > 0) {
                float sB = pB[0] + pB[1] + pB[2] + pB[3] + pB[4] + pB[5] + pB[6] + pB[7];
                sPB[warp * BB + lane] = sB;
            }
        }
        __syncthreads();                                       // S1

        // -------- CRITICAL C3: everything other CTAs consume --------------
        {
            const int p = un >> 1, r = un & 1;
            float syn = 0.0f;
            const float2* rr = redp + (size_t)p * PADB + ub;
            if (r == 0) {
                #pragma unroll
                for (int s = 0; s < NSLICE; ++s) syn += rr[(size_t)s * 8 * PADB].x;
            } else {
                #pragma unroll
                for (int s = 0; s < NSLICE; ++s) syn += rr[(size_t)s * 8 * PADB].y;
            }

            float h2 = hr + ((-hr + syn + F_IB + invalr * wi) - F_JEI * RIr) * invTau * F_DT;
            float R2 = rate_fn(h2);
            g_uxR[nxt][n0 + un][ub] = (un2 * xn2) * R2;

            float sR = R2;
            float sO = R2 * wo;
            #pragma unroll
            for (int d = 8; d > 0; d >>= 1) {
                sR += __shfl_xor_sync(0xFFFFFFFFu, sR, d, 16);
                sO += __shfl_xor_sync(0xFFFFFFFFu, sO, d, 16);
            }
            if ((tid & 15) == 0) {
                g_partialSumR[nxt][bid][ub] = sR;
                g_partialOut[nxt][bid][ub]  = sO;
            }

            hr = h2;
        }

        // -------- publish: release this CTA's epoch flag ------------------
        __syncthreads();                                       // S2
        if (tid == 0) {
            asm volatile("st.release.gpu.global.u32 [%0], %1;"
                         :: "l"(&g_flags[bid][0]), "r"((unsigned)(t + 1)) : "memory");
        }

        // -------- DEFERRED: overlaps next step's producer polling ---------
        {
            size_t o = (size_t)t * (BB * NN) + (size_t)ub * NN + (n0 + un);
            all_h[o] = hr;             // h(t+1)
            all_u[o] = un2;            // u(t+1)
            all_x[o] = xn2;            // x(t+1)

            // prefetch next step's input (cold line -> hide here)
            invalr = (t < TT - 1) ? inp[(size_t)(t + 1) * BB + ub] : 0.0f;

            // advance u,x for step t+1 using R(h(t+1))
            const float uc = un2, xc = xn2;
            const float Rc = rate_fn(hr);
            un2 = uc + ((F_U - uc) * invTauF + F_U * (1.0f - uc) * Rc) * F_DT;
            xn2 = xc + ((1.0f - xc) * invTauD - uc * xc * Rc) * F_DT;

            // h_I update (totR = sum rate(h_t), staged in sPA) + next RI
            float totR = 0.0f;
            #pragma unroll
            for (int w = 0; w < NWARP; ++w) totR += sPA[w * BB + ub];
            h_Ir = h_Ir + (-h_Ir + F_JIE * totR) * invTau * F_DT;
            RIr = rate_fn(h_Ir);

            if (bid == 0) {
                if (un == 0) all_hI[(size_t)t * BB + ub] = h_Ir;
                if (un == 1 && t > 0) {
                    float totB = 0.0f;
                    #pragma unroll
                    for (int w = 0; w < NWARP; ++w) totB += sPB[w * BB + ub];
                    outputs[(size_t)(t - 1) * BB + ub] = totB;
                }
            }
        }
    }

    // -------- epilogue: readout for the final step (buffer 0 = nxt(511)) -
    if (bid == 0) {
        waitProducers(warp, l8, (unsigned)TT);   // all partials of step 511 visible
        float sB = 0.0f;
        const float* pO = &g_partialOut[0][0][0];
        #pragma unroll
        for (int c = 0; c < 8; ++c) sB += __ldcg(pO + (warp * 8 + c) * BB + lane);
        sPartB[warp * BB + lane] = sB;
        __syncthreads();
        if (tid < BB) {
            float tot = 0.0f;
            #pragma unroll
            for (int w = 0; w < NWARP; ++w) tot += sPartB[w * BB + tid];
            outputs[(size_t)(TT - 1) * BB + tid] = tot;
        }
    }
}

#define SMEM_BYTES ((NN * JSTR) * 4 + (NSLICE * 8 * PADB) * 8 + (4 * NWARP * BB) * 4)

extern "C" void kernel_launch(void* const* d_in, const int* in_sizes, int n_in,
                              void* d_out, int out_size) {
    const float* inp   = (const float*)d_in[0];
    const float* W_in  = (const float*)d_in[1];
    const float* J     = (const float*)d_in[2];
    const float* W_out = (const float*)d_in[3];
    float* out = (float*)d_out;

    cudaFuncSetAttribute(step_kernel, cudaFuncAttributeMaxDynamicSharedMemorySize,
                         SMEM_BYTES);
    init_kernel<<<64, 256>>>();
    step_kernel<<<GRIDSZ, NTHR, SMEM_BYTES>>>(inp, W_in, J, W_out, out);
}

// round 17
// speedup vs baseline: 1.0366x; 1.0366x over previous
#include <cuda_runtime.h>

#define NN 2048
#define BB 32
#define TT 512
#define NT 16            // n-rows per CTA
#define GRIDSZ 128       // 128 CTAs * 16 rows = 2048
#define NTHR 512
#define NWARP 16
#define NSLICE 16        // 1 reduced slice per warp (xor8 + xor16 reduce)
#define PADB 34          // padded batch stride (float2 units) — >=32 and EVEN
#define JSTR 20          // Jt row stride in floats (16 data + 4 pad)

#define F_DT   1e-4f
#define F_U    0.3f
#define F_TAU  0.008f
#define F_TAUF 1.5f
#define F_TAUD 0.3f
#define F_ALPHA 1.5f
#define F_IB   8.0f
#define F_JEI  1.1f
#define F_JIE  2.2f

typedef unsigned long long ull;

// ---- persistent device state (double-buffered across steps) ----
__device__ float g_uxR[2][NN][BB];            // u*x*R(h), layout [m][b]
__device__ float g_partialSumR[2][GRIDSZ][BB];// per-CTA partial of sum_n R(h)
__device__ float g_partialOut[2][GRIDSZ][BB]; // per-CTA partial of readout
__device__ unsigned g_flags[GRIDSZ][32];      // per-CTA epoch flag (128B apart)

// packed fp32x2 fma, accumulator form: d = a*b + d
__device__ __forceinline__ void ffma2u(ull& d, ull a, ull b) {
    asm("fma.rn.f32x2 %0, %1, %2, %0;" : "+l"(d) : "l"(a), "l"(b));
}
__device__ __forceinline__ ull pack2(float v) {
    ull r; asm("mov.b64 %0, {%1, %1};" : "=l"(r) : "f"(v)); return r;
}

// R(h) = alpha * softplus(h/alpha), MUFU-based
__device__ __forceinline__ float rate_fn(float h) {
    float z = h * (1.0f / F_ALPHA);
    float sp = fmaxf(z, 0.0f) + __logf(1.0f + __expf(-fabsf(z)));
    return F_ALPHA * sp;
}

// warp-collective: wait until producer flags[8*warp .. 8*warp+7] >= target
__device__ __forceinline__ void waitProducers(int warp, int l8, unsigned target) {
    const unsigned* fp = &g_flags[warp * 8 + l8][0];
    unsigned v;
    do {
        asm volatile("ld.acquire.gpu.global.u32 %0, [%1];"
                     : "=r"(v) : "l"(fp) : "memory");
    } while (__any_sync(0xFFFFFFFFu, v < target));
}

__global__ void init_kernel() {
    int i = blockIdx.x * blockDim.x + threadIdx.x;
    int stride = gridDim.x * blockDim.x;
    const float R0 = F_ALPHA * 0.6931471805599453f;  // rate(0)
    const float v = F_U * R0;                        // u0*x0*R0
    float* u0p = &g_uxR[0][0][0];
    for (int k = i; k < NN * BB; k += stride) u0p[k] = v;
    float* ps = &g_partialSumR[0][0][0];
    for (int k = i; k < GRIDSZ * BB; k += stride) ps[k] = (float)NT * R0;
    unsigned* fl = &g_flags[0][0];
    for (int k = i; k < GRIDSZ * 32; k += stride) fl[k] = 0u;
}

__global__ void __launch_bounds__(NTHR, 1)
step_kernel(const float* __restrict__ inp, const float* __restrict__ W_in,
            const float* __restrict__ J,   const float* __restrict__ W_out,
            float* __restrict__ out)
{
    extern __shared__ float smem[];
    float*  Jt     = smem;                             // [NN][JSTR] transposed J
    float2* redp   = (float2*)(Jt + (size_t)NN * JSTR);// [NSLICE][8 np][PADB]
    float*  sPartA = (float*)(redp + (size_t)NSLICE * 8 * PADB); // [NWARP][BB]
    float*  sPartB = sPartA + NWARP * BB;              // [NWARP][BB]

    float* all_h  = out;
    float* all_u  = out + (size_t)TT * BB * NN;
    float* all_x  = out + (size_t)2 * TT * BB * NN;
    float* all_hI = out + (size_t)3 * TT * BB * NN;
    float* outputs = all_hI + (size_t)TT * BB;

    const int tid  = threadIdx.x;
    const int bid  = blockIdx.x;
    const int warp = tid >> 5;
    const int lane = tid & 31;
    const int strm = lane >> 3;        // 0..3  m-stream within warp
    const int l8   = lane & 7;         // 0..7  -> batches [4*l8, 4*l8+4)
    const int n0   = bid * NT;

    // update-phase mapping: thread -> (batch ub, single neuron n0+un)
    const int ub = tid >> 4;           // 0..31
    const int un = tid & 15;           // 0..15

    const float invTau  = 1.0f / F_TAU;
    const float invTauF = 1.0f / F_TAUF;
    const float invTauD = 1.0f / F_TAUD;

    // ---- stage J transposed ONCE: Jt[m][n_local], row stride JSTR ----
    #pragma unroll 4
    for (int it = 0; it < 16; ++it) {
        int idx = tid + it * NTHR;     // 0..8191 (16 rows * 512 float4)
        int r   = idx >> 9;            // 0..15
        int c4  = idx & 511;           // float4 col (m/4)
        float4 v = *(const float4*)(J + (size_t)(n0 + r) * NN + c4 * 4);
        float* dst = Jt + (size_t)(c4 * 4) * JSTR + r;
        dst[0 * JSTR] = v.x;
        dst[1 * JSTR] = v.y;
        dst[2 * JSTR] = v.z;
        dst[3 * JSTR] = v.w;
    }

    const float wi = W_in[n0 + un];
    const float wo = W_out[n0 + un];
    __syncthreads();

    // persistent per-thread state (h_I replicated, deterministic identical)
    float hr = 0.0f, h_Ir = 0.0f;
    const float R0c = rate_fn(0.0f);
    float RIr = R0c;                                       // rate(h_I(0))
    float un2 = F_U + (F_U * (1.0f - F_U) * R0c) * F_DT;   // u(1)
    float xn2 = 1.0f - (F_U * R0c) * F_DT;                 // x(1)
    float invalr = inp[ub];                                 // inp(0)

    // GEMM: iteration mi processes m = warp*128 + mi*4 + strm
    const int mfirst = warp * 128 + strm;
    const ull ONE2 = pack2(1.0f);

    for (int t = 0; t < TT; ++t) {
        const int cur = t & 1, nxt = cur ^ 1;
        const bool duty = (bid == (t & (GRIDSZ - 1)));   // rotating readout duty

        __syncthreads();                                   // S0: deferred smem
                                                           // reads done before
                                                           // this step's staging
        // ---- wait for THIS warp's 8 producer CTAs (epoch >= t) ----------
        waitProducers(warp, l8, (unsigned)t);

        // ===== GEMM: 4 m-streams x 8 lanes x 4 batches x 16 n ===========
        const float* ubaseF = &g_uxR[cur][0][0] + (size_t)mfirst * BB + 4 * l8;

        ull acc[8][4];
        #pragma unroll
        for (int p = 0; p < 8; ++p)
            #pragma unroll
            for (int b = 0; b < 4; ++b) acc[p][b] = 0ull;

        float4 upf[2];
        upf[0] = __ldcg((const float4*)(ubaseF + 0 * 4 * BB));
        upf[1] = __ldcg((const float4*)(ubaseF + 1 * 4 * BB));

        #pragma unroll 4
        for (int mi = 0; mi < 32; ++mi) {
            const float4 u4 = upf[mi & 1];
            if (mi < 30)
                upf[mi & 1] = __ldcg((const float4*)(ubaseF + (size_t)(mi + 2) * 4 * BB));

            const int m = mfirst + mi * 4;
            const ulonglong2* jq = (const ulonglong2*)(Jt + (size_t)m * JSTR);
            ulonglong2 q0 = jq[0];
            ulonglong2 q1 = jq[1];
            ulonglong2 q2 = jq[2];
            ulonglong2 q3 = jq[3];

            const ull ub0 = pack2(u4.x);
            const ull ub1 = pack2(u4.y);
            const ull ub2p = pack2(u4.z);
            const ull ub3 = pack2(u4.w);

            ffma2u(acc[0][0], q0.x, ub0); ffma2u(acc[0][1], q0.x, ub1);
            ffma2u(acc[0][2], q0.x, ub2p); ffma2u(acc[0][3], q0.x, ub3);
            ffma2u(acc[1][0], q0.y, ub0); ffma2u(acc[1][1], q0.y, ub1);
            ffma2u(acc[1][2], q0.y, ub2p); ffma2u(acc[1][3], q0.y, ub3);
            ffma2u(acc[2][0], q1.x, ub0); ffma2u(acc[2][1], q1.x, ub1);
            ffma2u(acc[2][2], q1.x, ub2p); ffma2u(acc[2][3], q1.x, ub3);
            ffma2u(acc[3][0], q1.y, ub0); ffma2u(acc[3][1], q1.y, ub1);
            ffma2u(acc[3][2], q1.y, ub2p); ffma2u(acc[3][3], q1.y, ub3);
            ffma2u(acc[4][0], q2.x, ub0); ffma2u(acc[4][1], q2.x, ub1);
            ffma2u(acc[4][2], q2.x, ub2p); ffma2u(acc[4][3], q2.x, ub3);
            ffma2u(acc[5][0], q2.y, ub0); ffma2u(acc[5][1], q2.y, ub1);
            ffma2u(acc[5][2], q2.y, ub2p); ffma2u(acc[5][3], q2.y, ub3);
            ffma2u(acc[6][0], q3.x, ub0); ffma2u(acc[6][1], q3.x, ub1);
            ffma2u(acc[6][2], q3.x, ub2p); ffma2u(acc[6][3], q3.x, ub3);
            ffma2u(acc[7][0], q3.y, ub0); ffma2u(acc[7][1], q3.y, ub1);
            ffma2u(acc[7][2], q3.y, ub2p); ffma2u(acc[7][3], q3.y, ub3);
        }

        // ----- reduce the 4 streams in-register (same n, same batches) ---
        #pragma unroll
        for (int p = 0; p < 8; ++p)
            #pragma unroll
            for (int b = 0; b < 4; ++b) {
                ull o1 = __shfl_xor_sync(0xFFFFFFFFu, acc[p][b], 8);
                ffma2u(acc[p][b], o1, ONE2);
                ull o2 = __shfl_xor_sync(0xFFFFFFFFu, acc[p][b], 16);
                ffma2u(acc[p][b], o2, ONE2);
            }

        // lanes 0..7 hold full warp partials; store slice = warp
        if (strm == 0) {
            float2* rw = redp + (size_t)warp * 8 * PADB + 4 * l8;
            #pragma unroll
            for (int p = 0; p < 8; ++p) {
                ulonglong2 v0; v0.x = acc[p][0]; v0.y = acc[p][1];
                ulonglong2 v1; v1.x = acc[p][2]; v1.y = acc[p][3];
                *(ulonglong2*)(rw + p * PADB)     = v0;
                *(ulonglong2*)(rw + p * PADB + 2) = v1;
            }
        }

        // -------- C1: stage cross-CTA partials (producers 8w..8w+7) ------
        {
            float sA = 0.0f;
            const float* pS = &g_partialSumR[cur][0][0];
            #pragma unroll
            for (int c = 0; c < 8; ++c) sA += __ldcg(pS + (warp * 8 + c) * BB + lane);
            sPartA[warp * BB + lane] = sA;
            if (duty && t > 0) {
                float sB = 0.0f;
                const float* pO = &g_partialOut[cur][0][0];
                #pragma unroll
                for (int c = 0; c < 8; ++c) sB += __ldcg(pO + (warp * 8 + c) * BB + lane);
                sPartB[warp * BB + lane] = sB;
            }
        }
        __syncthreads();                                       // S1

        // -------- CRITICAL C3: everything other CTAs consume --------------
        {
            const int p = un >> 1, r = un & 1;
            float syn = 0.0f;
            const float2* rr = redp + (size_t)p * PADB + ub;
            if (r == 0) {
                #pragma unroll
                for (int s = 0; s < NSLICE; ++s) syn += rr[(size_t)s * 8 * PADB].x;
            } else {
                #pragma unroll
                for (int s = 0; s < NSLICE; ++s) syn += rr[(size_t)s * 8 * PADB].y;
            }

            float h2 = hr + ((-hr + syn + F_IB + invalr * wi) - F_JEI * RIr) * invTau * F_DT;
            float R2 = rate_fn(h2);
            g_uxR[nxt][n0 + un][ub] = (un2 * xn2) * R2;

            float sR = R2;
            float sO = R2 * wo;
            #pragma unroll
            for (int d = 8; d > 0; d >>= 1) {
                sR += __shfl_xor_sync(0xFFFFFFFFu, sR, d, 16);
                sO += __shfl_xor_sync(0xFFFFFFFFu, sO, d, 16);
            }
            if ((tid & 15) == 0) {
                g_partialSumR[nxt][bid][ub] = sR;
                g_partialOut[nxt][bid][ub]  = sO;
            }

            hr = h2;
        }

        // -------- publish: release this CTA's epoch flag ------------------
        __syncthreads();                                       // S2
        if (tid == 0) {
            asm volatile("st.release.gpu.global.u32 [%0], %1;"
                         :: "l"(&g_flags[bid][0]), "r"((unsigned)(t + 1)) : "memory");
        }

        // -------- DEFERRED: overlapped with other CTAs' polling -----------
        {
            size_t o = (size_t)t * (BB * NN) + (size_t)ub * NN + (n0 + un);
            all_h[o] = hr;             // h(t+1)
            all_u[o] = un2;            // u(t+1)
            all_x[o] = xn2;            // x(t+1)

            // prefetch next step's input (cold line -> hide here)
            invalr = (t < TT - 1) ? inp[(size_t)(t + 1) * BB + ub] : 0.0f;

            // advance u,x for step t+1 using R(h(t+1))
            const float uc = un2, xc = xn2;
            const float Rc = rate_fn(hr);
            un2 = uc + ((F_U - uc) * invTauF + F_U * (1.0f - uc) * Rc) * F_DT;
            xn2 = xc + ((1.0f - xc) * invTauD - uc * xc * Rc) * F_DT;

            // h_I update (totR = sum rate(h_t), staged in sPartA) + next RI
            float totR = 0.0f;
            #pragma unroll
            for (int w = 0; w < NWARP; ++w) totR += sPartA[w * BB + ub];
            h_Ir = h_Ir + (-h_Ir + F_JIE * totR) * invTau * F_DT;
            RIr = rate_fn(h_Ir);

            if (duty) {
                if (un == 0) all_hI[(size_t)t * BB + ub] = h_Ir;
                if (un == 1 && t > 0) {
                    float totB = 0.0f;
                    #pragma unroll
                    for (int w = 0; w < NWARP; ++w) totB += sPartB[w * BB + ub];
                    outputs[(size_t)(t - 1) * BB + ub] = totB;
                }
            }
        }
    }

    // -------- epilogue: readout for the final step (buffer 0 = nxt(511)) -
    if (bid == 0) {
        waitProducers(warp, l8, (unsigned)TT);   // all partials of step 511 visible
        float sB = 0.0f;
        const float* pO = &g_partialOut[0][0][0];
        #pragma unroll
        for (int c = 0; c < 8; ++c) sB += __ldcg(pO + (warp * 8 + c) * BB + lane);
        sPartB[warp * BB + lane] = sB;
        __syncthreads();
        if (tid < BB) {
            float tot = 0.0f;
            #pragma unroll
            for (int w = 0; w < NWARP; ++w) tot += sPartB[w * BB + tid];
            outputs[(size_t)(TT - 1) * BB + tid] = tot;
        }
    }
}

#define SMEM_BYTES ((NN * JSTR) * 4 + (NSLICE * 8 * PADB) * 8 + (NWARP * BB * 2) * 4)

extern "C" void kernel_launch(void* const* d_in, const int* in_sizes, int n_in,
                              void* d_out, int out_size) {
    const float* inp   = (const float*)d_in[0];
    const float* W_in  = (const float*)d_in[1];
    const float* J     = (const float*)d_in[2];
    const float* W_out = (const float*)d_in[3];
    float* out = (float*)d_out;

    cudaFuncSetAttribute(step_kernel, cudaFuncAttributeMaxDynamicSharedMemorySize,
                         SMEM_BYTES);
    init_kernel<<<64, 256>>>();
    step_kernel<<<GRIDSZ, NTHR, SMEM_BYTES>>>(inp, W_in, J, W_out, out);
}